// round 1
// baseline (speedup 1.0000x reference)
#include <cuda_runtime.h>
#include <cuda_bf16.h>

// RelaxedProd: B=32, N=128, D=4096, shared_errors = 128 = N1 = N2.
// With s == N2 == N1 the zero-padding in the reference collapses:
//   self_errors   = e1  (transposed curr_errors)
//   factor_errors = e2  (transposed curr_errors_2)
// and the two moveaxis transposes cancel, so everything is elementwise /
// column-reduced in the native (B, N, D) layout:
//   out_lin[b,n,d]  = ch[b,d]*ce2[b,n,d] + ch2[b,d]*ce1[b,n,d]
//   prod_sum[b,d]   = sum_n ce1*ce2
//   abs_prod[b,d]   = sum_n |ce1*ce2|
//   abs_sum[b,d]    = sum_n |ce1|
//   new_head[b,d]   = ch*ch2 + 0.5*prod_sum
//   qe[b,d]         = abs_sum^2 - 0.5*abs_prod
//   out_adv[b,n,d]  = qe[b,d] * adv[b,n,d]
// Output layout: [ new_head (B*D) | new_errors (B, 2N, D) flattened ],
// where rows 0..N-1 of each batch are out_lin and rows N..2N-1 are out_adv.

#ifndef RP_B
#define RP_B 32
#endif
#define RP_N 128
#define RP_D 4096

__global__ __launch_bounds__(256, 8)
void relaxed_prod_kernel(const float* __restrict__ ch,
                         const float* __restrict__ ce1,
                         const float* __restrict__ ch2,
                         const float* __restrict__ ce2,
                         const float* __restrict__ adv,
                         float* __restrict__ out_head,
                         float* __restrict__ out_err) {
    const int t = blockIdx.x * blockDim.x + threadIdx.x;   // 0 .. B*D-1
    const int b = t >> 12;          // t / D  (D = 4096)
    const int d = t & (RP_D - 1);   // t % D

    const long long base  = (long long)b * RP_N * RP_D + d;       // input column base
    const long long obase = (long long)b * 2 * RP_N * RP_D + d;   // output column base

    const float h1 = ch[t];
    const float h2 = ch2[t];

    float abs_sum  = 0.0f;
    float prod_sum = 0.0f;
    float abs_prod = 0.0f;

    // Pass 1: lin-err output + three reductions over n in one sweep.
    #pragma unroll 8
    for (int n = 0; n < RP_N; ++n) {
        const long long off = base + (long long)n * RP_D;
        const float a = ce1[off];
        const float c = ce2[off];
        out_err[obase + (long long)n * RP_D] = h1 * c + h2 * a;
        const float p = a * c;
        prod_sum += p;
        abs_prod += fabsf(p);
        abs_sum  += fabsf(a);
    }

    out_head[t] = h1 * h2 + 0.5f * prod_sum;
    const float qe = abs_sum * abs_sum - 0.5f * abs_prod;

    // Pass 2: stream adv_errors scaled by qe into the second half of new_errors.
    const long long obase2 = obase + (long long)RP_N * RP_D;
    #pragma unroll 8
    for (int n = 0; n < RP_N; ++n) {
        out_err[obase2 + (long long)n * RP_D] = qe * adv[base + (long long)n * RP_D];
    }
}

extern "C" void kernel_launch(void* const* d_in, const int* in_sizes, int n_in,
                              void* d_out, int out_size) {
    const float* ch  = (const float*)d_in[0];   // curr_head     (B, D)
    const float* ce1 = (const float*)d_in[1];   // curr_errors   (B, N, D)
    const float* ch2 = (const float*)d_in[2];   // curr_head_2   (B, D)
    const float* ce2 = (const float*)d_in[3];   // curr_errors_2 (B, N, D)
    const float* adv = (const float*)d_in[4];   // adv_errors    (B, N, D)
    // d_in[5] = shared_errors (== N, padding collapses — not needed at runtime)

    float* out_head = (float*)d_out;                     // B*D elements
    float* out_err  = (float*)d_out + RP_B * RP_D;       // B * 2N * D elements

    const int total   = RP_B * RP_D;     // 131072 threads, one per (b,d) column
    const int threads = 256;
    const int blocks  = total / threads; // 512
    relaxed_prod_kernel<<<blocks, threads>>>(ch, ce1, ch2, ce2, adv,
                                             out_head, out_err);
}